// round 16
// baseline (speedup 1.0000x reference)
#include <cuda_runtime.h>
#include <cuda_bf16.h>
#include <cstdint>

#define HID 2048
#define STATE 128
#define HEADS 64
#define HEADDIM 64
#define INTER 4096
#define CONV_DIM 4352
#define PROJ_DIM 8512
#define NTOK 4096
#define SEQ 2048
#define EPSV 1e-5f
#define NSEG 16
#define SEGLEN (SEQ / NSEG)   // 128

// ---------------- scratch ----------------
__device__ float g_xn[(size_t)NTOK * HID];
__device__ float g_proj[(size_t)NTOK * PROJ_DIM];
__device__ float g_xs[(size_t)NTOK * INTER];
__device__ float g_Bm[(size_t)NTOK * STATE];
__device__ float g_Cm[(size_t)NTOK * STATE];
__device__ float g_dt[(size_t)NTOK * HEADS];
__device__ float g_dA[(size_t)NTOK * HEADS];
__device__ float g_y[(size_t)NTOK * INTER];
__device__ float g_yn[(size_t)NTOK * INTER];
__device__ float g_wa[(size_t)PROJ_DIM * HID];
__device__ float g_wb[(size_t)HID * INTER];
__device__ float g_Fst[(size_t)2 * HEADS * NSEG * HEADDIM * STATE];  // 64MB
__device__ float g_Pseg[2 * HEADS * NSEG];

// ---------------- helpers ----------------
__device__ __forceinline__ uint32_t f2tf(float f) {
    uint32_t r;
    asm("cvt.rna.tf32.f32 %0, %1;" : "=r"(r) : "f"(f));
    return r;
}

__device__ __forceinline__ uint32_t smem_u32(const void* p) {
    uint32_t a;
    asm("{ .reg .u64 t; cvta.to.shared.u64 t, %1; cvt.u32.u64 %0, t; }" : "=r"(a) : "l"(p));
    return a;
}

#define CP_ASYNC16(saddr, gptr) \
    asm volatile("cp.async.cg.shared.global [%0], [%1], 16;" :: "r"(saddr), "l"(gptr) : "memory")
#define CP_COMMIT() asm volatile("cp.async.commit_group;" ::: "memory")
#define CP_WAIT1()  asm volatile("cp.async.wait_group 1;" ::: "memory")

__device__ __forceinline__ float fast_silu(float a) {
    return __fdividef(a, 1.f + __expf(-a));
}

__device__ __forceinline__ float block_reduce_sum(float v) {
    __shared__ float sh[32];
    int lane = threadIdx.x & 31, w = threadIdx.x >> 5;
    #pragma unroll
    for (int o = 16; o; o >>= 1) v += __shfl_xor_sync(0xffffffffu, v, o);
    if (lane == 0) sh[w] = v;
    __syncthreads();
    int nw = blockDim.x >> 5;
    float t = (threadIdx.x < (unsigned)nw) ? sh[threadIdx.x] : 0.f;
    if (w == 0) {
        #pragma unroll
        for (int o = 16; o; o >>= 1) t += __shfl_xor_sync(0xffffffffu, t, o);
        if (lane == 0) sh[0] = t;
    }
    __syncthreads();
    return sh[0];
}

// f32x2 packed math
typedef unsigned long long ull;
__device__ __forceinline__ ull pack2(float lo, float hi) {
    ull r; asm("mov.b64 %0, {%1,%2};" : "=l"(r) : "f"(lo), "f"(hi)); return r;
}
__device__ __forceinline__ ull mul2(ull a, ull b) {
    ull r; asm("mul.rn.f32x2 %0, %1, %2;" : "=l"(r) : "l"(a), "l"(b)); return r;
}
__device__ __forceinline__ ull fma2(ull a, ull b, ull c) {
    ull r; asm("fma.rn.f32x2 %0, %1, %2, %3;" : "=l"(r) : "l"(a), "l"(b), "l"(c)); return r;
}
__device__ __forceinline__ ull add2(ull a, ull b) {
    ull r; asm("add.rn.f32x2 %0, %1, %2;" : "=l"(r) : "l"(a), "l"(b)); return r;
}
__device__ __forceinline__ void unpack2(ull v, float& lo, float& hi) {
    asm("mov.b64 {%0,%1}, %2;" : "=f"(lo), "=f"(hi) : "l"(v));
}

// ---------------- stage 0: convert weights to tf32 bits ----------------
__global__ __launch_bounds__(256) void tf32_cvt_kernel(
    const float* __restrict__ in, float* __restrict__ out, int n4) {
    int i = blockIdx.x * 256 + threadIdx.x;
    if (i >= n4) return;
    float4 v = ((const float4*)in)[i];
    uint4 u;
    u.x = f2tf(v.x); u.y = f2tf(v.y); u.z = f2tf(v.z); u.w = f2tf(v.w);
    ((uint4*)out)[i] = u;
}

// ---------------- stage 1: input rmsnorm (float4) ----------------
__global__ __launch_bounds__(256) void rmsnorm_in_kernel(
    const float* __restrict__ x, const float* __restrict__ w) {
    int row = blockIdx.x;
    const float4* xr = (const float4*)(x + (size_t)row * HID);
    const float4* w4 = (const float4*)w;
    float4 vals[2];
    float ss = 0.f;
    #pragma unroll
    for (int i = 0; i < 2; i++) {
        int idx = threadIdx.x + i * 256;
        float4 v = xr[idx];
        vals[i] = v;
        ss += v.x * v.x + v.y * v.y + v.z * v.z + v.w * v.w;
    }
    float tot = block_reduce_sum(ss);
    float scale = rsqrtf(tot * (1.f / HID) + EPSV);
    uint4* orow = (uint4*)(g_xn + (size_t)row * HID);
    #pragma unroll
    for (int i = 0; i < 2; i++) {
        int idx = threadIdx.x + i * 256;
        float4 ww = w4[idx];
        uint4 o;
        o.x = f2tf(vals[i].x * scale * ww.x);
        o.y = f2tf(vals[i].y * scale * ww.y);
        o.z = f2tf(vals[i].z * scale * ww.z);
        o.w = f2tf(vals[i].w * scale * ww.w);
        orow[idx] = o;
    }
}

// ---------------- TF32 NT GEMM (unchanged from R12) ----------------
#define BK 32
#define LDK 36
#define STAGE_FLOATS (128 * LDK)
#define GEMM_SMEM (3 * 2 * STAGE_FLOATS * 4)

__global__ __launch_bounds__(128, 2) void gemm_tf32_nt(
    const float* __restrict__ A, const float* __restrict__ Bw,
    float* __restrict__ C, const float* __restrict__ Res,
    int M, int N, int K) {
    extern __shared__ float smf[];
    float* As = smf;
    float* Bs = smf + 3 * STAGE_FLOATS;
    uint32_t sA = smem_u32(As), sB = smem_u32(Bs);

    int tid = threadIdx.x;
    int mBase = blockIdx.y * 128, nBase = blockIdx.x * 128;
    int wid = tid >> 5, lane = tid & 31;
    int wm = wid >> 1, wn = wid & 1;
    int g = lane >> 2, tg = lane & 3;
    int nk = K / BK;

    float acc[4][8][4];
    #pragma unroll
    for (int a = 0; a < 4; a++)
        #pragma unroll
        for (int b = 0; b < 8; b++)
            #pragma unroll
            for (int c = 0; c < 4; c++) acc[a][b][c] = 0.f;

    auto issue_tile = [&](int kt, int s) {
        size_t gk = (size_t)kt * BK;
        #pragma unroll
        for (int i = 0; i < 8; i++) {
            int idx = tid + i * 128;
            int row = idx >> 3, c4 = (idx & 7) * 4;
            uint32_t sa = sA + (uint32_t)(s * STAGE_FLOATS + row * LDK + c4) * 4u;
            CP_ASYNC16(sa, A + (size_t)(mBase + row) * K + gk + c4);
        }
        #pragma unroll
        for (int i = 0; i < 8; i++) {
            int idx = tid + i * 128;
            int row = idx >> 3, c4 = (idx & 7) * 4;
            if (nBase + row < N) {
                uint32_t sb2 = sB + (uint32_t)(s * STAGE_FLOATS + row * LDK + c4) * 4u;
                CP_ASYNC16(sb2, Bw + (size_t)(nBase + row) * K + gk + c4);
            }
        }
        CP_COMMIT();
    };

    issue_tile(0, 0);
    issue_tile(1, 1);

    int s_next = 2;
    for (int kt = 0; kt < nk; ++kt) {
        CP_WAIT1();
        __syncthreads();

        if (kt + 2 < nk) {
            issue_tile(kt + 2, s_next);
        } else {
            CP_COMMIT();
        }
        s_next++; if (s_next == 3) s_next = 0;

        int cur = kt % 3;
        const float* a_st = As + cur * STAGE_FLOATS;
        const float* b_st = Bs + cur * STAGE_FLOATS;
        #pragma unroll
        for (int kk = 0; kk < 4; ++kk) {
            uint32_t af[4][4], bf[8][2];
            int col = kk * 8 + tg;
            #pragma unroll
            for (int mt = 0; mt < 4; ++mt) {
                int row = wm * 64 + mt * 16 + g;
                af[mt][0] = __float_as_uint(a_st[row * LDK + col]);
                af[mt][1] = __float_as_uint(a_st[(row + 8) * LDK + col]);
                af[mt][2] = __float_as_uint(a_st[row * LDK + col + 4]);
                af[mt][3] = __float_as_uint(a_st[(row + 8) * LDK + col + 4]);
            }
            #pragma unroll
            for (int nt = 0; nt < 8; ++nt) {
                int nrow = wn * 64 + nt * 8 + g;
                bf[nt][0] = __float_as_uint(b_st[nrow * LDK + col]);
                bf[nt][1] = __float_as_uint(b_st[nrow * LDK + col + 4]);
            }
            #pragma unroll
            for (int mt = 0; mt < 4; ++mt)
                #pragma unroll
                for (int nt = 0; nt < 8; ++nt) {
                    asm volatile(
                        "mma.sync.aligned.m16n8k8.row.col.f32.tf32.tf32.f32 "
                        "{%0,%1,%2,%3},{%4,%5,%6,%7},{%8,%9},{%0,%1,%2,%3};\n"
                        : "+f"(acc[mt][nt][0]), "+f"(acc[mt][nt][1]),
                          "+f"(acc[mt][nt][2]), "+f"(acc[mt][nt][3])
                        : "r"(af[mt][0]), "r"(af[mt][1]), "r"(af[mt][2]), "r"(af[mt][3]),
                          "r"(bf[nt][0]), "r"(bf[nt][1]));
                }
        }
    }

    #pragma unroll
    for (int mt = 0; mt < 4; ++mt) {
        int row0 = mBase + wm * 64 + mt * 16 + g;
        #pragma unroll
        for (int nt = 0; nt < 8; ++nt) {
            int col = nBase + wn * 64 + nt * 8 + tg * 2;
            if (col < N) {
                float v0 = acc[mt][nt][0];
                float v1 = acc[mt][nt][1];
                float v2 = acc[mt][nt][2];
                float v3 = acc[mt][nt][3];
                int row1 = row0 + 8;
                bool c1 = (col + 1 < N);
                if (Res) {
                    v0 += Res[(size_t)row0 * N + col];
                    if (c1) v1 += Res[(size_t)row0 * N + col + 1];
                    v2 += Res[(size_t)row1 * N + col];
                    if (c1) v3 += Res[(size_t)row1 * N + col + 1];
                }
                C[(size_t)row0 * N + col] = v0;
                if (c1) C[(size_t)row0 * N + col + 1] = v1;
                C[(size_t)row1 * N + col] = v2;
                if (c1) C[(size_t)row1 * N + col + 1] = v3;
            }
        }
    }
}

// ---------------- stage 3: conv, 16 tokens/block, fully unrolled ----------------
__global__ __launch_bounds__(64) void conv_kernel(
    const float* __restrict__ conv_w, const float* __restrict__ conv_b) {
    int c = (blockIdx.x * 64 + threadIdx.x) * 4;
    int t0 = blockIdx.y * 16;
    float4 wt[4];
    {
        float4 a = *(const float4*)&conv_w[(c + 0) * 4];
        float4 b = *(const float4*)&conv_w[(c + 1) * 4];
        float4 d = *(const float4*)&conv_w[(c + 2) * 4];
        float4 e = *(const float4*)&conv_w[(c + 3) * 4];
        wt[0] = make_float4(a.x, b.x, d.x, e.x);
        wt[1] = make_float4(a.y, b.y, d.y, e.y);
        wt[2] = make_float4(a.z, b.z, d.z, e.z);
        wt[3] = make_float4(a.w, b.w, d.w, e.w);
    }
    float4 bias = *(const float4*)&conv_b[c];
    const float* col = g_proj + INTER + c;
    float4 h0, h1, h2;
    if ((t0 & (SEQ - 1)) == 0) {
        h0 = h1 = h2 = make_float4(0.f, 0.f, 0.f, 0.f);
    } else {
        h0 = *(const float4*)&col[(size_t)(t0 - 3) * PROJ_DIM];
        h1 = *(const float4*)&col[(size_t)(t0 - 2) * PROJ_DIM];
        h2 = *(const float4*)&col[(size_t)(t0 - 1) * PROJ_DIM];
    }
    // pre-load all 16 token inputs (independent -> high MLP)
    float4 xs[16];
    #pragma unroll
    for (int i = 0; i < 16; i++)
        xs[i] = *(const float4*)&col[(size_t)(t0 + i) * PROJ_DIM];
    #pragma unroll
    for (int i = 0; i < 16; i++) {
        int t = t0 + i;
        float4 xc = xs[i];
        float4 v;
        v.x = fast_silu(bias.x + wt[0].x * h0.x + wt[1].x * h1.x + wt[2].x * h2.x + wt[3].x * xc.x);
        v.y = fast_silu(bias.y + wt[0].y * h0.y + wt[1].y * h1.y + wt[2].y * h2.y + wt[3].y * xc.y);
        v.z = fast_silu(bias.z + wt[0].z * h0.z + wt[1].z * h1.z + wt[2].z * h2.z + wt[3].z * xc.z);
        v.w = fast_silu(bias.w + wt[0].w * h0.w + wt[1].w * h1.w + wt[2].w * h2.w + wt[3].w * xc.w);
        if (c < INTER)
            *(float4*)&g_xs[(size_t)t * INTER + c] = v;
        else if (c < INTER + STATE)
            *(float4*)&g_Bm[(size_t)t * STATE + (c - INTER)] = v;
        else
            *(float4*)&g_Cm[(size_t)t * STATE + (c - INTER - STATE)] = v;
        h0 = h1; h1 = h2; h2 = xc;
    }
}

// ---------------- stage 4: dt / dA ----------------
__global__ __launch_bounds__(256) void dt_kernel(
    const float* __restrict__ dt_bias, const float* __restrict__ A_log) {
    int i = blockIdx.x * 256 + threadIdx.x;
    if (i >= NTOK * HEADS) return;
    int h = i & (HEADS - 1);
    int tok = i >> 6;
    float raw = g_proj[(size_t)tok * PROJ_DIM + INTER + CONV_DIM + h];
    float s = raw + dt_bias[h];
    float dtv = (s > 20.f) ? s : log1pf(expf(s));
    float Aval = -expf(A_log[h]);
    g_dt[i] = dtv;
    g_dA[i] = expf(dtv * Aval);
}

// ---------------- segment dA products ----------------
__global__ __launch_bounds__(256) void pseg_kernel() {
    int idx = blockIdx.x * 256 + threadIdx.x;
    if (idx >= 2 * HEADS * NSEG) return;
    int seg = idx & (NSEG - 1);
    int h = (idx >> 4) & (HEADS - 1);
    int b = idx >> 10;
    size_t t0 = (size_t)b * SEQ + seg * SEGLEN;
    float prod = 1.f;
    for (int k = 0; k < SEGLEN; k++)
        prod *= g_dA[(t0 + k) * HEADS + h];
    g_Pseg[idx] = prod;
}

// ---------------- segmented scan passes ----------------
#define TCH 16
template<bool PASS2>
__global__ __launch_bounds__(256) void scan_pass(const float* __restrict__ Dv) {
    __shared__ float sBC[2][TCH][2 * STATE];
    int h = blockIdx.x, b = blockIdx.y, seg = blockIdx.z;
    int tidx = threadIdx.x;
    int lane = tidx & 31, w = tidx >> 5;
    int pi = lane & 7, nc = lane >> 3;
    int p = w * 8 + pi;

    ull st2[16];
    size_t fslot = ((size_t)(b * HEADS + h) * NSEG);
    size_t foff = (size_t)p * STATE + nc * 32;
    if (PASS2 && seg > 0) {
        const ull* Fp = (const ull*)(g_Fst + (fslot + seg - 1) * (HEADDIM * STATE) + foff);
        #pragma unroll
        for (int i = 0; i < 16; i++) st2[i] = Fp[i];
    } else {
        #pragma unroll
        for (int i = 0; i < 16; i++) st2[i] = 0ull;
    }

    float Dh = Dv[h];
    size_t tok0 = (size_t)b * SEQ + seg * SEGLEN;
    const float* xp = g_xs + tok0 * INTER + h * HEADDIM + p;
    const float4* Bg = (const float4*)(g_Bm + tok0 * STATE);
    const float4* Cg = (const float4*)(g_Cm + tok0 * STATE);
    const float* dAp = g_dA + tok0 * HEADS + h;
    const float* dtp = g_dt + tok0 * HEADS + h;
    float* yo = g_y + tok0 * INTER + h * HEADDIM + p;

    int lt0 = (tidx + 0) >> 5, lq0 = (tidx + 0) & 31;
    int lt1 = (tidx + 256) >> 5, lq1 = (tidx + 256) & 31;

    // prologue chunk 0
    {
        *(float4*)&sBC[0][lt0][lq0 * 4] = Bg[(size_t)lt0 * 32 + lq0];
        *(float4*)&sBC[0][lt1][lq1 * 4] = Bg[(size_t)lt1 * 32 + lq1];
        if (PASS2) {
            *(float4*)&sBC[0][lt0][STATE + lq0 * 4] = Cg[(size_t)lt0 * 32 + lq0];
            *(float4*)&sBC[0][lt1][STATE + lq1 * 4] = Cg[(size_t)lt1 * 32 + lq1];
        }
    }
    __syncthreads();

    int nch = SEGLEN / TCH;   // 8
    for (int ck = 0; ck < nch; ck++) {
        int buf = ck & 1;
        float4 nb0, nb1, nc0, nc1;
        bool more = (ck + 1 < nch);
        if (more) {
            int t0 = (ck + 1) * TCH;
            nb0 = Bg[(size_t)(t0 + lt0) * 32 + lq0];
            nb1 = Bg[(size_t)(t0 + lt1) * 32 + lq1];
            if (PASS2) {
                nc0 = Cg[(size_t)(t0 + lt0) * 32 + lq0];
                nc1 = Cg[(size_t)(t0 + lt1) * 32 + lq1];
            }
        }
        int tb = ck * TCH;
        #pragma unroll
        for (int ti = 0; ti < TCH; ti++) {
            int t = tb + ti;
            float dAv = dAp[(size_t)t * HEADS];
            float dtv = dtp[(size_t)t * HEADS];
            float xv = xp[(size_t)t * INTER];
            float xdt = xv * dtv;
            ull dA2 = pack2(dAv, dAv);
            ull xdt2 = pack2(xdt, xdt);
            const ulonglong2* B4 = (const ulonglong2*)&sBC[buf][ti][nc * 32];
            if (PASS2) {
                const ulonglong2* C4 = (const ulonglong2*)&sBC[buf][ti][STATE + nc * 32];
                ull ya = pack2(0.f, 0.f), yb = ya, yc = ya, yd = ya;
                #pragma unroll
                for (int j = 0; j < 4; j++) {
                    ulonglong2 bv0 = B4[2 * j];
                    ulonglong2 cv0 = C4[2 * j];
                    ulonglong2 bv1 = B4[2 * j + 1];
                    ulonglong2 cv1 = C4[2 * j + 1];
                    st2[4 * j + 0] = fma2(st2[4 * j + 0], dA2, mul2(xdt2, bv0.x));
                    ya             = fma2(st2[4 * j + 0], cv0.x, ya);
                    st2[4 * j + 1] = fma2(st2[4 * j + 1], dA2, mul2(xdt2, bv0.y));
                    yb             = fma2(st2[4 * j + 1], cv0.y, yb);
                    st2[4 * j + 2] = fma2(st2[4 * j + 2], dA2, mul2(xdt2, bv1.x));
                    yc             = fma2(st2[4 * j + 2], cv1.x, yc);
                    st2[4 * j + 3] = fma2(st2[4 * j + 3], dA2, mul2(xdt2, bv1.y));
                    yd             = fma2(st2[4 * j + 3], cv1.y, yd);
                }
                ull ysum = add2(add2(ya, yb), add2(yc, yd));
                float ylo, yhi;
                unpack2(ysum, ylo, yhi);
                float ys = ylo + yhi;
                ys += __shfl_xor_sync(0xffffffffu, ys, 8);
                ys += __shfl_xor_sync(0xffffffffu, ys, 16);
                if (nc == 0) yo[(size_t)t * INTER] = ys + Dh * xv;
            } else {
                #pragma unroll
                for (int j = 0; j < 8; j++) {
                    ulonglong2 bv = B4[j];
                    st2[2 * j]     = fma2(st2[2 * j],     dA2, mul2(xdt2, bv.x));
                    st2[2 * j + 1] = fma2(st2[2 * j + 1], dA2, mul2(xdt2, bv.y));
                }
            }
        }
        __syncthreads();
        if (more) {
            int nbuf = buf ^ 1;
            *(float4*)&sBC[nbuf][lt0][lq0 * 4] = nb0;
            *(float4*)&sBC[nbuf][lt1][lq1 * 4] = nb1;
            if (PASS2) {
                *(float4*)&sBC[nbuf][lt0][STATE + lq0 * 4] = nc0;
                *(float4*)&sBC[nbuf][lt1][STATE + lq1 * 4] = nc1;
            }
            __syncthreads();
        }
    }

    if (!PASS2) {
        ull* Fp = (ull*)(g_Fst + (fslot + seg) * (HEADDIM * STATE) + foff);
        #pragma unroll
        for (int i = 0; i < 16; i++) Fp[i] = st2[i];
    }
}

// ---------------- combine: S_j = F_j + P_j * S_{j-1} (in place) ----------------
__global__ __launch_bounds__(256) void scan_combine() {
    int h = blockIdx.x, b = blockIdx.y;
    int tid = threadIdx.x;
    size_t base = ((size_t)(b * HEADS + h) * NSEG) * (HEADDIM * STATE) + (size_t)tid * 32;
    const float* Ps = g_Pseg + (b * HEADS + h) * NSEG;
    float4 S[8];
    #pragma unroll
    for (int i = 0; i < 8; i++) S[i] = *(float4*)(g_Fst + base + i * 4);
    for (int j = 1; j < NSEG; j++) {
        float Pj = Ps[j];
        float* Fj = g_Fst + base + (size_t)j * (HEADDIM * STATE);
        #pragma unroll
        for (int i = 0; i < 8; i++) {
            float4 F = *(float4*)(Fj + i * 4);
            S[i].x = F.x + Pj * S[i].x;
            S[i].y = F.y + Pj * S[i].y;
            S[i].z = F.z + Pj * S[i].z;
            S[i].w = F.w + Pj * S[i].w;
            *(float4*)(Fj + i * 4) = S[i];
        }
    }
}

// ---------------- stage 6: gated rmsnorm (float4) ----------------
__global__ __launch_bounds__(256) void gatenorm_kernel(const float* __restrict__ gnw) {
    int row = blockIdx.x;
    const float4* yrow = (const float4*)(g_y + (size_t)row * INTER);
    const float4* grow = (const float4*)(g_proj + (size_t)row * PROJ_DIM);
    const float4* gw4 = (const float4*)gnw;
    float4 vals[4];
    float ss = 0.f;
    #pragma unroll
    for (int i = 0; i < 4; i++) {
        int idx = threadIdx.x + i * 256;
        float4 gt = grow[idx];
        float4 yv = yrow[idx];
        float4 v;
        v.x = yv.x * fast_silu(gt.x);
        v.y = yv.y * fast_silu(gt.y);
        v.z = yv.z * fast_silu(gt.z);
        v.w = yv.w * fast_silu(gt.w);
        vals[i] = v;
        ss += v.x * v.x + v.y * v.y + v.z * v.z + v.w * v.w;
    }
    float tot = block_reduce_sum(ss);
    float scale = rsqrtf(tot * (1.f / INTER) + EPSV);
    uint4* orow = (uint4*)(g_yn + (size_t)row * INTER);
    #pragma unroll
    for (int i = 0; i < 4; i++) {
        int idx = threadIdx.x + i * 256;
        float4 ww = gw4[idx];
        uint4 o;
        o.x = f2tf(vals[i].x * scale * ww.x);
        o.y = f2tf(vals[i].y * scale * ww.y);
        o.z = f2tf(vals[i].z * scale * ww.z);
        o.w = f2tf(vals[i].w * scale * ww.w);
        orow[idx] = o;
    }
}

// ---------------- launch ----------------
extern "C" void kernel_launch(void* const* d_in, const int* in_sizes, int n_in,
                              void* d_out, int out_size) {
    const float* hidden  = (const float*)d_in[0];
    const float* norm_w  = (const float*)d_in[1];
    const float* in_proj = (const float*)d_in[2];
    const float* conv_w  = (const float*)d_in[3];
    const float* conv_b  = (const float*)d_in[4];
    const float* dt_bias = (const float*)d_in[5];
    const float* A_log   = (const float*)d_in[6];
    const float* Dvec    = (const float*)d_in[7];
    const float* gnw     = (const float*)d_in[8];
    const float* out_w   = (const float*)d_in[9];

    float *p_xn, *p_proj, *p_yn, *p_wa, *p_wb;
    cudaGetSymbolAddress((void**)&p_xn, g_xn);
    cudaGetSymbolAddress((void**)&p_proj, g_proj);
    cudaGetSymbolAddress((void**)&p_yn, g_yn);
    cudaGetSymbolAddress((void**)&p_wa, g_wa);
    cudaGetSymbolAddress((void**)&p_wb, g_wb);

    cudaFuncSetAttribute(gemm_tf32_nt, cudaFuncAttributeMaxDynamicSharedMemorySize, GEMM_SMEM);

    int n4a = (PROJ_DIM * HID) / 4;
    tf32_cvt_kernel<<<(n4a + 255) / 256, 256>>>(in_proj, p_wa, n4a);
    int n4b = (HID * INTER) / 4;
    tf32_cvt_kernel<<<(n4b + 255) / 256, 256>>>(out_w, p_wb, n4b);

    rmsnorm_in_kernel<<<NTOK, 256>>>(hidden, norm_w);

    gemm_tf32_nt<<<dim3((PROJ_DIM + 127) / 128, NTOK / 128), 128, GEMM_SMEM>>>(
        p_xn, p_wa, p_proj, nullptr, NTOK, PROJ_DIM, HID);

    conv_kernel<<<dim3(CONV_DIM / 4 / 64, NTOK / 16), 64>>>(conv_w, conv_b);

    dt_kernel<<<(NTOK * HEADS) / 256, 256>>>(dt_bias, A_log);

    pseg_kernel<<<(2 * HEADS * NSEG + 255) / 256, 256>>>();

    scan_pass<false><<<dim3(HEADS, 2, NSEG), 256>>>(Dvec);

    scan_combine<<<dim3(HEADS, 2), 256>>>();

    scan_pass<true><<<dim3(HEADS, 2, NSEG), 256>>>(Dvec);

    gatenorm_kernel<<<NTOK, 256>>>(gnw);

    gemm_tf32_nt<<<dim3(HID / 128, NTOK / 128), 128, GEMM_SMEM>>>(
        p_yn, p_wb, (float*)d_out, hidden, NTOK, HID, INTER);
}

// round 17
// speedup vs baseline: 1.0055x; 1.0055x over previous
#include <cuda_runtime.h>
#include <cuda_bf16.h>
#include <cstdint>

#define HID 2048
#define STATE 128
#define HEADS 64
#define HEADDIM 64
#define INTER 4096
#define CONV_DIM 4352
#define PROJ_DIM 8512
#define NTOK 4096
#define SEQ 2048
#define EPSV 1e-5f
#define NSEG 16
#define SEGLEN (SEQ / NSEG)   // 128

// ---------------- scratch ----------------
__device__ float g_xn[(size_t)NTOK * HID];
__device__ float g_proj[(size_t)NTOK * PROJ_DIM];
__device__ float g_xs[(size_t)NTOK * INTER];
__device__ float g_Bm[(size_t)NTOK * STATE];
__device__ float g_Cm[(size_t)NTOK * STATE];
__device__ float g_dt[(size_t)NTOK * HEADS];
__device__ float g_dA[(size_t)NTOK * HEADS];
__device__ float g_y[(size_t)NTOK * INTER];
__device__ float g_yn[(size_t)NTOK * INTER];
__device__ float g_wa[(size_t)PROJ_DIM * HID];
__device__ float g_wb[(size_t)HID * INTER];
__device__ float g_Fst[(size_t)2 * HEADS * NSEG * HEADDIM * STATE];  // 64MB
__device__ float g_Pseg[2 * HEADS * NSEG];

// ---------------- helpers ----------------
__device__ __forceinline__ uint32_t f2tf(float f) {
    uint32_t r;
    asm("cvt.rna.tf32.f32 %0, %1;" : "=r"(r) : "f"(f));
    return r;
}

__device__ __forceinline__ uint32_t smem_u32(const void* p) {
    uint32_t a;
    asm("{ .reg .u64 t; cvta.to.shared.u64 t, %1; cvt.u32.u64 %0, t; }" : "=r"(a) : "l"(p));
    return a;
}

#define CP_ASYNC16(saddr, gptr) \
    asm volatile("cp.async.cg.shared.global [%0], [%1], 16;" :: "r"(saddr), "l"(gptr) : "memory")
#define CP_COMMIT() asm volatile("cp.async.commit_group;" ::: "memory")
#define CP_WAIT1()  asm volatile("cp.async.wait_group 1;" ::: "memory")

__device__ __forceinline__ float fast_silu(float a) {
    return __fdividef(a, 1.f + __expf(-a));
}

__device__ __forceinline__ float block_reduce_sum(float v) {
    __shared__ float sh[32];
    int lane = threadIdx.x & 31, w = threadIdx.x >> 5;
    #pragma unroll
    for (int o = 16; o; o >>= 1) v += __shfl_xor_sync(0xffffffffu, v, o);
    if (lane == 0) sh[w] = v;
    __syncthreads();
    int nw = blockDim.x >> 5;
    float t = (threadIdx.x < (unsigned)nw) ? sh[threadIdx.x] : 0.f;
    if (w == 0) {
        #pragma unroll
        for (int o = 16; o; o >>= 1) t += __shfl_xor_sync(0xffffffffu, t, o);
        if (lane == 0) sh[0] = t;
    }
    __syncthreads();
    return sh[0];
}

// f32x2 packed math
typedef unsigned long long ull;
__device__ __forceinline__ ull pack2(float lo, float hi) {
    ull r; asm("mov.b64 %0, {%1,%2};" : "=l"(r) : "f"(lo), "f"(hi)); return r;
}
__device__ __forceinline__ ull mul2(ull a, ull b) {
    ull r; asm("mul.rn.f32x2 %0, %1, %2;" : "=l"(r) : "l"(a), "l"(b)); return r;
}
__device__ __forceinline__ ull fma2(ull a, ull b, ull c) {
    ull r; asm("fma.rn.f32x2 %0, %1, %2, %3;" : "=l"(r) : "l"(a), "l"(b), "l"(c)); return r;
}
__device__ __forceinline__ ull add2(ull a, ull b) {
    ull r; asm("add.rn.f32x2 %0, %1, %2;" : "=l"(r) : "l"(a), "l"(b)); return r;
}
__device__ __forceinline__ void unpack2(ull v, float& lo, float& hi) {
    asm("mov.b64 {%0,%1}, %2;" : "=f"(lo), "=f"(hi) : "l"(v));
}

// ---------------- stage 0: convert weights to tf32 bits ----------------
__global__ __launch_bounds__(256) void tf32_cvt_kernel(
    const float* __restrict__ in, float* __restrict__ out, int n4) {
    int i = blockIdx.x * 256 + threadIdx.x;
    if (i >= n4) return;
    float4 v = ((const float4*)in)[i];
    uint4 u;
    u.x = f2tf(v.x); u.y = f2tf(v.y); u.z = f2tf(v.z); u.w = f2tf(v.w);
    ((uint4*)out)[i] = u;
}

// ---------------- stage 1: input rmsnorm (float4) ----------------
__global__ __launch_bounds__(256) void rmsnorm_in_kernel(
    const float* __restrict__ x, const float* __restrict__ w) {
    int row = blockIdx.x;
    const float4* xr = (const float4*)(x + (size_t)row * HID);
    const float4* w4 = (const float4*)w;
    float4 vals[2];
    float ss = 0.f;
    #pragma unroll
    for (int i = 0; i < 2; i++) {
        int idx = threadIdx.x + i * 256;
        float4 v = xr[idx];
        vals[i] = v;
        ss += v.x * v.x + v.y * v.y + v.z * v.z + v.w * v.w;
    }
    float tot = block_reduce_sum(ss);
    float scale = rsqrtf(tot * (1.f / HID) + EPSV);
    uint4* orow = (uint4*)(g_xn + (size_t)row * HID);
    #pragma unroll
    for (int i = 0; i < 2; i++) {
        int idx = threadIdx.x + i * 256;
        float4 ww = w4[idx];
        uint4 o;
        o.x = f2tf(vals[i].x * scale * ww.x);
        o.y = f2tf(vals[i].y * scale * ww.y);
        o.z = f2tf(vals[i].z * scale * ww.z);
        o.w = f2tf(vals[i].w * scale * ww.w);
        orow[idx] = o;
    }
}

// ---------------- TF32 NT GEMM (unchanged from R12) ----------------
#define BK 32
#define LDK 36
#define STAGE_FLOATS (128 * LDK)
#define GEMM_SMEM (3 * 2 * STAGE_FLOATS * 4)

__global__ __launch_bounds__(128, 2) void gemm_tf32_nt(
    const float* __restrict__ A, const float* __restrict__ Bw,
    float* __restrict__ C, const float* __restrict__ Res,
    int M, int N, int K) {
    extern __shared__ float smf[];
    float* As = smf;
    float* Bs = smf + 3 * STAGE_FLOATS;
    uint32_t sA = smem_u32(As), sB = smem_u32(Bs);

    int tid = threadIdx.x;
    int mBase = blockIdx.y * 128, nBase = blockIdx.x * 128;
    int wid = tid >> 5, lane = tid & 31;
    int wm = wid >> 1, wn = wid & 1;
    int g = lane >> 2, tg = lane & 3;
    int nk = K / BK;

    float acc[4][8][4];
    #pragma unroll
    for (int a = 0; a < 4; a++)
        #pragma unroll
        for (int b = 0; b < 8; b++)
            #pragma unroll
            for (int c = 0; c < 4; c++) acc[a][b][c] = 0.f;

    auto issue_tile = [&](int kt, int s) {
        size_t gk = (size_t)kt * BK;
        #pragma unroll
        for (int i = 0; i < 8; i++) {
            int idx = tid + i * 128;
            int row = idx >> 3, c4 = (idx & 7) * 4;
            uint32_t sa = sA + (uint32_t)(s * STAGE_FLOATS + row * LDK + c4) * 4u;
            CP_ASYNC16(sa, A + (size_t)(mBase + row) * K + gk + c4);
        }
        #pragma unroll
        for (int i = 0; i < 8; i++) {
            int idx = tid + i * 128;
            int row = idx >> 3, c4 = (idx & 7) * 4;
            if (nBase + row < N) {
                uint32_t sb2 = sB + (uint32_t)(s * STAGE_FLOATS + row * LDK + c4) * 4u;
                CP_ASYNC16(sb2, Bw + (size_t)(nBase + row) * K + gk + c4);
            }
        }
        CP_COMMIT();
    };

    issue_tile(0, 0);
    issue_tile(1, 1);

    int s_next = 2;
    for (int kt = 0; kt < nk; ++kt) {
        CP_WAIT1();
        __syncthreads();

        if (kt + 2 < nk) {
            issue_tile(kt + 2, s_next);
        } else {
            CP_COMMIT();
        }
        s_next++; if (s_next == 3) s_next = 0;

        int cur = kt % 3;
        const float* a_st = As + cur * STAGE_FLOATS;
        const float* b_st = Bs + cur * STAGE_FLOATS;
        #pragma unroll
        for (int kk = 0; kk < 4; ++kk) {
            uint32_t af[4][4], bf[8][2];
            int col = kk * 8 + tg;
            #pragma unroll
            for (int mt = 0; mt < 4; ++mt) {
                int row = wm * 64 + mt * 16 + g;
                af[mt][0] = __float_as_uint(a_st[row * LDK + col]);
                af[mt][1] = __float_as_uint(a_st[(row + 8) * LDK + col]);
                af[mt][2] = __float_as_uint(a_st[row * LDK + col + 4]);
                af[mt][3] = __float_as_uint(a_st[(row + 8) * LDK + col + 4]);
            }
            #pragma unroll
            for (int nt = 0; nt < 8; ++nt) {
                int nrow = wn * 64 + nt * 8 + g;
                bf[nt][0] = __float_as_uint(b_st[nrow * LDK + col]);
                bf[nt][1] = __float_as_uint(b_st[nrow * LDK + col + 4]);
            }
            #pragma unroll
            for (int mt = 0; mt < 4; ++mt)
                #pragma unroll
                for (int nt = 0; nt < 8; ++nt) {
                    asm volatile(
                        "mma.sync.aligned.m16n8k8.row.col.f32.tf32.tf32.f32 "
                        "{%0,%1,%2,%3},{%4,%5,%6,%7},{%8,%9},{%0,%1,%2,%3};\n"
                        : "+f"(acc[mt][nt][0]), "+f"(acc[mt][nt][1]),
                          "+f"(acc[mt][nt][2]), "+f"(acc[mt][nt][3])
                        : "r"(af[mt][0]), "r"(af[mt][1]), "r"(af[mt][2]), "r"(af[mt][3]),
                          "r"(bf[nt][0]), "r"(bf[nt][1]));
                }
        }
    }

    #pragma unroll
    for (int mt = 0; mt < 4; ++mt) {
        int row0 = mBase + wm * 64 + mt * 16 + g;
        #pragma unroll
        for (int nt = 0; nt < 8; ++nt) {
            int col = nBase + wn * 64 + nt * 8 + tg * 2;
            if (col < N) {
                float v0 = acc[mt][nt][0];
                float v1 = acc[mt][nt][1];
                float v2 = acc[mt][nt][2];
                float v3 = acc[mt][nt][3];
                int row1 = row0 + 8;
                bool c1 = (col + 1 < N);
                if (Res) {
                    v0 += Res[(size_t)row0 * N + col];
                    if (c1) v1 += Res[(size_t)row0 * N + col + 1];
                    v2 += Res[(size_t)row1 * N + col];
                    if (c1) v3 += Res[(size_t)row1 * N + col + 1];
                }
                C[(size_t)row0 * N + col] = v0;
                if (c1) C[(size_t)row0 * N + col + 1] = v1;
                C[(size_t)row1 * N + col] = v2;
                if (c1) C[(size_t)row1 * N + col + 1] = v3;
            }
        }
    }
}

// ---------------- stage 3: conv, 16 tokens/block, fully unrolled ----------------
__global__ __launch_bounds__(64) void conv_kernel(
    const float* __restrict__ conv_w, const float* __restrict__ conv_b) {
    int c = (blockIdx.x * 64 + threadIdx.x) * 4;
    int t0 = blockIdx.y * 16;
    float4 wt[4];
    {
        float4 a = *(const float4*)&conv_w[(c + 0) * 4];
        float4 b = *(const float4*)&conv_w[(c + 1) * 4];
        float4 d = *(const float4*)&conv_w[(c + 2) * 4];
        float4 e = *(const float4*)&conv_w[(c + 3) * 4];
        wt[0] = make_float4(a.x, b.x, d.x, e.x);
        wt[1] = make_float4(a.y, b.y, d.y, e.y);
        wt[2] = make_float4(a.z, b.z, d.z, e.z);
        wt[3] = make_float4(a.w, b.w, d.w, e.w);
    }
    float4 bias = *(const float4*)&conv_b[c];
    const float* col = g_proj + INTER + c;
    float4 h0, h1, h2;
    if ((t0 & (SEQ - 1)) == 0) {
        h0 = h1 = h2 = make_float4(0.f, 0.f, 0.f, 0.f);
    } else {
        h0 = *(const float4*)&col[(size_t)(t0 - 3) * PROJ_DIM];
        h1 = *(const float4*)&col[(size_t)(t0 - 2) * PROJ_DIM];
        h2 = *(const float4*)&col[(size_t)(t0 - 1) * PROJ_DIM];
    }
    // pre-load all 16 token inputs (independent -> high MLP)
    float4 xs[16];
    #pragma unroll
    for (int i = 0; i < 16; i++)
        xs[i] = *(const float4*)&col[(size_t)(t0 + i) * PROJ_DIM];
    #pragma unroll
    for (int i = 0; i < 16; i++) {
        int t = t0 + i;
        float4 xc = xs[i];
        float4 v;
        v.x = fast_silu(bias.x + wt[0].x * h0.x + wt[1].x * h1.x + wt[2].x * h2.x + wt[3].x * xc.x);
        v.y = fast_silu(bias.y + wt[0].y * h0.y + wt[1].y * h1.y + wt[2].y * h2.y + wt[3].y * xc.y);
        v.z = fast_silu(bias.z + wt[0].z * h0.z + wt[1].z * h1.z + wt[2].z * h2.z + wt[3].z * xc.z);
        v.w = fast_silu(bias.w + wt[0].w * h0.w + wt[1].w * h1.w + wt[2].w * h2.w + wt[3].w * xc.w);
        if (c < INTER)
            *(float4*)&g_xs[(size_t)t * INTER + c] = v;
        else if (c < INTER + STATE)
            *(float4*)&g_Bm[(size_t)t * STATE + (c - INTER)] = v;
        else
            *(float4*)&g_Cm[(size_t)t * STATE + (c - INTER - STATE)] = v;
        h0 = h1; h1 = h2; h2 = xc;
    }
}

// ---------------- stage 4: dt / dA ----------------
__global__ __launch_bounds__(256) void dt_kernel(
    const float* __restrict__ dt_bias, const float* __restrict__ A_log) {
    int i = blockIdx.x * 256 + threadIdx.x;
    if (i >= NTOK * HEADS) return;
    int h = i & (HEADS - 1);
    int tok = i >> 6;
    float raw = g_proj[(size_t)tok * PROJ_DIM + INTER + CONV_DIM + h];
    float s = raw + dt_bias[h];
    float dtv = (s > 20.f) ? s : log1pf(expf(s));
    float Aval = -expf(A_log[h]);
    g_dt[i] = dtv;
    g_dA[i] = expf(dtv * Aval);
}

// ---------------- segment dA products ----------------
__global__ __launch_bounds__(256) void pseg_kernel() {
    int idx = blockIdx.x * 256 + threadIdx.x;
    if (idx >= 2 * HEADS * NSEG) return;
    int seg = idx & (NSEG - 1);
    int h = (idx >> 4) & (HEADS - 1);
    int b = idx >> 10;
    size_t t0 = (size_t)b * SEQ + seg * SEGLEN;
    float prod = 1.f;
    for (int k = 0; k < SEGLEN; k++)
        prod *= g_dA[(t0 + k) * HEADS + h];
    g_Pseg[idx] = prod;
}

// ---------------- segmented scan passes ----------------
#define TCH 16
template<bool PASS2>
__global__ __launch_bounds__(256) void scan_pass(const float* __restrict__ Dv) {
    __shared__ float sBC[2][TCH][2 * STATE];
    int h = blockIdx.x, b = blockIdx.y, seg = blockIdx.z;
    int tidx = threadIdx.x;
    int lane = tidx & 31, w = tidx >> 5;
    int pi = lane & 7, nc = lane >> 3;
    int p = w * 8 + pi;

    ull st2[16];
    size_t fslot = ((size_t)(b * HEADS + h) * NSEG);
    size_t foff = (size_t)p * STATE + nc * 32;
    if (PASS2 && seg > 0) {
        const ull* Fp = (const ull*)(g_Fst + (fslot + seg - 1) * (HEADDIM * STATE) + foff);
        #pragma unroll
        for (int i = 0; i < 16; i++) st2[i] = Fp[i];
    } else {
        #pragma unroll
        for (int i = 0; i < 16; i++) st2[i] = 0ull;
    }

    float Dh = Dv[h];
    size_t tok0 = (size_t)b * SEQ + seg * SEGLEN;
    const float* xp = g_xs + tok0 * INTER + h * HEADDIM + p;
    const float4* Bg = (const float4*)(g_Bm + tok0 * STATE);
    const float4* Cg = (const float4*)(g_Cm + tok0 * STATE);
    const float* dAp = g_dA + tok0 * HEADS + h;
    const float* dtp = g_dt + tok0 * HEADS + h;
    float* yo = g_y + tok0 * INTER + h * HEADDIM + p;

    int lt0 = (tidx + 0) >> 5, lq0 = (tidx + 0) & 31;
    int lt1 = (tidx + 256) >> 5, lq1 = (tidx + 256) & 31;

    // prologue chunk 0
    {
        *(float4*)&sBC[0][lt0][lq0 * 4] = Bg[(size_t)lt0 * 32 + lq0];
        *(float4*)&sBC[0][lt1][lq1 * 4] = Bg[(size_t)lt1 * 32 + lq1];
        if (PASS2) {
            *(float4*)&sBC[0][lt0][STATE + lq0 * 4] = Cg[(size_t)lt0 * 32 + lq0];
            *(float4*)&sBC[0][lt1][STATE + lq1 * 4] = Cg[(size_t)lt1 * 32 + lq1];
        }
    }
    __syncthreads();

    int nch = SEGLEN / TCH;   // 8
    for (int ck = 0; ck < nch; ck++) {
        int buf = ck & 1;
        float4 nb0, nb1, nc0, nc1;
        bool more = (ck + 1 < nch);
        if (more) {
            int t0 = (ck + 1) * TCH;
            nb0 = Bg[(size_t)(t0 + lt0) * 32 + lq0];
            nb1 = Bg[(size_t)(t0 + lt1) * 32 + lq1];
            if (PASS2) {
                nc0 = Cg[(size_t)(t0 + lt0) * 32 + lq0];
                nc1 = Cg[(size_t)(t0 + lt1) * 32 + lq1];
            }
        }
        int tb = ck * TCH;
        #pragma unroll
        for (int ti = 0; ti < TCH; ti++) {
            int t = tb + ti;
            float dAv = dAp[(size_t)t * HEADS];
            float dtv = dtp[(size_t)t * HEADS];
            float xv = xp[(size_t)t * INTER];
            float xdt = xv * dtv;
            ull dA2 = pack2(dAv, dAv);
            ull xdt2 = pack2(xdt, xdt);
            const ulonglong2* B4 = (const ulonglong2*)&sBC[buf][ti][nc * 32];
            if (PASS2) {
                const ulonglong2* C4 = (const ulonglong2*)&sBC[buf][ti][STATE + nc * 32];
                ull ya = pack2(0.f, 0.f), yb = ya, yc = ya, yd = ya;
                #pragma unroll
                for (int j = 0; j < 4; j++) {
                    ulonglong2 bv0 = B4[2 * j];
                    ulonglong2 cv0 = C4[2 * j];
                    ulonglong2 bv1 = B4[2 * j + 1];
                    ulonglong2 cv1 = C4[2 * j + 1];
                    st2[4 * j + 0] = fma2(st2[4 * j + 0], dA2, mul2(xdt2, bv0.x));
                    ya             = fma2(st2[4 * j + 0], cv0.x, ya);
                    st2[4 * j + 1] = fma2(st2[4 * j + 1], dA2, mul2(xdt2, bv0.y));
                    yb             = fma2(st2[4 * j + 1], cv0.y, yb);
                    st2[4 * j + 2] = fma2(st2[4 * j + 2], dA2, mul2(xdt2, bv1.x));
                    yc             = fma2(st2[4 * j + 2], cv1.x, yc);
                    st2[4 * j + 3] = fma2(st2[4 * j + 3], dA2, mul2(xdt2, bv1.y));
                    yd             = fma2(st2[4 * j + 3], cv1.y, yd);
                }
                ull ysum = add2(add2(ya, yb), add2(yc, yd));
                float ylo, yhi;
                unpack2(ysum, ylo, yhi);
                float ys = ylo + yhi;
                ys += __shfl_xor_sync(0xffffffffu, ys, 8);
                ys += __shfl_xor_sync(0xffffffffu, ys, 16);
                if (nc == 0) yo[(size_t)t * INTER] = ys + Dh * xv;
            } else {
                #pragma unroll
                for (int j = 0; j < 8; j++) {
                    ulonglong2 bv = B4[j];
                    st2[2 * j]     = fma2(st2[2 * j],     dA2, mul2(xdt2, bv.x));
                    st2[2 * j + 1] = fma2(st2[2 * j + 1], dA2, mul2(xdt2, bv.y));
                }
            }
        }
        __syncthreads();
        if (more) {
            int nbuf = buf ^ 1;
            *(float4*)&sBC[nbuf][lt0][lq0 * 4] = nb0;
            *(float4*)&sBC[nbuf][lt1][lq1 * 4] = nb1;
            if (PASS2) {
                *(float4*)&sBC[nbuf][lt0][STATE + lq0 * 4] = nc0;
                *(float4*)&sBC[nbuf][lt1][STATE + lq1 * 4] = nc1;
            }
            __syncthreads();
        }
    }

    if (!PASS2) {
        ull* Fp = (ull*)(g_Fst + (fslot + seg) * (HEADDIM * STATE) + foff);
        #pragma unroll
        for (int i = 0; i < 16; i++) Fp[i] = st2[i];
    }
}

// ---------------- combine: S_j = F_j + P_j * S_{j-1} (in place) ----------------
__global__ __launch_bounds__(256) void scan_combine() {
    int h = blockIdx.x, b = blockIdx.y;
    int tid = threadIdx.x;
    size_t base = ((size_t)(b * HEADS + h) * NSEG) * (HEADDIM * STATE) + (size_t)tid * 32;
    const float* Ps = g_Pseg + (b * HEADS + h) * NSEG;
    float4 S[8];
    #pragma unroll
    for (int i = 0; i < 8; i++) S[i] = *(float4*)(g_Fst + base + i * 4);
    for (int j = 1; j < NSEG; j++) {
        float Pj = Ps[j];
        float* Fj = g_Fst + base + (size_t)j * (HEADDIM * STATE);
        #pragma unroll
        for (int i = 0; i < 8; i++) {
            float4 F = *(float4*)(Fj + i * 4);
            S[i].x = F.x + Pj * S[i].x;
            S[i].y = F.y + Pj * S[i].y;
            S[i].z = F.z + Pj * S[i].z;
            S[i].w = F.w + Pj * S[i].w;
            *(float4*)(Fj + i * 4) = S[i];
        }
    }
}

// ---------------- stage 6: gated rmsnorm (float4) ----------------
__global__ __launch_bounds__(256) void gatenorm_kernel(const float* __restrict__ gnw) {
    int row = blockIdx.x;
    const float4* yrow = (const float4*)(g_y + (size_t)row * INTER);
    const float4* grow = (const float4*)(g_proj + (size_t)row * PROJ_DIM);
    const float4* gw4 = (const float4*)gnw;
    float4 vals[4];
    float ss = 0.f;
    #pragma unroll
    for (int i = 0; i < 4; i++) {
        int idx = threadIdx.x + i * 256;
        float4 gt = grow[idx];
        float4 yv = yrow[idx];
        float4 v;
        v.x = yv.x * fast_silu(gt.x);
        v.y = yv.y * fast_silu(gt.y);
        v.z = yv.z * fast_silu(gt.z);
        v.w = yv.w * fast_silu(gt.w);
        vals[i] = v;
        ss += v.x * v.x + v.y * v.y + v.z * v.z + v.w * v.w;
    }
    float tot = block_reduce_sum(ss);
    float scale = rsqrtf(tot * (1.f / INTER) + EPSV);
    uint4* orow = (uint4*)(g_yn + (size_t)row * INTER);
    #pragma unroll
    for (int i = 0; i < 4; i++) {
        int idx = threadIdx.x + i * 256;
        float4 ww = gw4[idx];
        uint4 o;
        o.x = f2tf(vals[i].x * scale * ww.x);
        o.y = f2tf(vals[i].y * scale * ww.y);
        o.z = f2tf(vals[i].z * scale * ww.z);
        o.w = f2tf(vals[i].w * scale * ww.w);
        orow[idx] = o;
    }
}

// ---------------- launch ----------------
extern "C" void kernel_launch(void* const* d_in, const int* in_sizes, int n_in,
                              void* d_out, int out_size) {
    const float* hidden  = (const float*)d_in[0];
    const float* norm_w  = (const float*)d_in[1];
    const float* in_proj = (const float*)d_in[2];
    const float* conv_w  = (const float*)d_in[3];
    const float* conv_b  = (const float*)d_in[4];
    const float* dt_bias = (const float*)d_in[5];
    const float* A_log   = (const float*)d_in[6];
    const float* Dvec    = (const float*)d_in[7];
    const float* gnw     = (const float*)d_in[8];
    const float* out_w   = (const float*)d_in[9];

    float *p_xn, *p_proj, *p_yn, *p_wa, *p_wb;
    cudaGetSymbolAddress((void**)&p_xn, g_xn);
    cudaGetSymbolAddress((void**)&p_proj, g_proj);
    cudaGetSymbolAddress((void**)&p_yn, g_yn);
    cudaGetSymbolAddress((void**)&p_wa, g_wa);
    cudaGetSymbolAddress((void**)&p_wb, g_wb);

    cudaFuncSetAttribute(gemm_tf32_nt, cudaFuncAttributeMaxDynamicSharedMemorySize, GEMM_SMEM);

    int n4a = (PROJ_DIM * HID) / 4;
    tf32_cvt_kernel<<<(n4a + 255) / 256, 256>>>(in_proj, p_wa, n4a);
    int n4b = (HID * INTER) / 4;
    tf32_cvt_kernel<<<(n4b + 255) / 256, 256>>>(out_w, p_wb, n4b);

    rmsnorm_in_kernel<<<NTOK, 256>>>(hidden, norm_w);

    gemm_tf32_nt<<<dim3((PROJ_DIM + 127) / 128, NTOK / 128), 128, GEMM_SMEM>>>(
        p_xn, p_wa, p_proj, nullptr, NTOK, PROJ_DIM, HID);

    conv_kernel<<<dim3(CONV_DIM / 4 / 64, NTOK / 16), 64>>>(conv_w, conv_b);

    dt_kernel<<<(NTOK * HEADS) / 256, 256>>>(dt_bias, A_log);

    pseg_kernel<<<(2 * HEADS * NSEG + 255) / 256, 256>>>();

    scan_pass<false><<<dim3(HEADS, 2, NSEG), 256>>>(Dvec);

    scan_combine<<<dim3(HEADS, 2), 256>>>();

    scan_pass<true><<<dim3(HEADS, 2, NSEG), 256>>>(Dvec);

    gatenorm_kernel<<<NTOK, 256>>>(gnw);

    gemm_tf32_nt<<<dim3(HID / 128, NTOK / 128), 128, GEMM_SMEM>>>(
        p_yn, p_wb, (float*)d_out, hidden, NTOK, HID, INTER);
}